// round 15
// baseline (speedup 1.0000x reference)
#include <cuda_runtime.h>
#include <cuda_bf16.h>
#include <math.h>

typedef unsigned long long ull;

#define B_SZ 4
#define T_SZ 12800
#define M_ROWS (B_SZ*T_SZ)   // 51200
#define CCTA 16              // CTAs per batch chain (512 threads each)

// ---------------- static device scratch (no allocation anywhere) ----------------
__device__ __align__(256) float g_aux[4*128*50];
__device__ __align__(256) float g_up1[4*80*216];
__device__ __align__(256) float g_up2[4*80*1728];
__device__ __align__(256) float g_up3[4*80*13824];
__device__ __align__(256) float g_in0[M_ROWS*128];
__device__ __align__(256) float g_iw[512*128];
__device__ __align__(256) float g_h[M_ROWS*512];
__device__ __align__(256) float g_xp[M_ROWS*1536];
__device__ __align__(256) float g_cat[M_ROWS*544];
__device__ __align__(256) float g_f1[M_ROWS*512];
__device__ __align__(256) float g_f2[M_ROWS*512];
// per-phase, per-batch double-buffered h state: [(phase*4+b)][buf][512]
__device__ __align__(256) float g_stb[8][2][512];
// per-phase, per-batch barrier counters, one 128B line each
__device__ __align__(128) unsigned g_cnt[8*32];

// ---------------- f32x2 / sync / math helpers ----------------
__device__ __forceinline__ ull pack2(float x, float y) {
    ull r; asm("mov.b64 %0, {%1,%2};" : "=l"(r) : "f"(x), "f"(y)); return r;
}
__device__ __forceinline__ ull dup2(float x) {
    ull r; unsigned u = __float_as_uint(x);
    asm("mov.b64 %0, {%1,%1};" : "=l"(r) : "r"(u)); return r;
}
__device__ __forceinline__ float2 unpack2(ull v) {
    float2 f; asm("mov.b64 {%0,%1}, %2;" : "=f"(f.x), "=f"(f.y) : "l"(v)); return f;
}
__device__ __forceinline__ void fma2(ull& d, ull a, ull b) {
    asm("fma.rn.f32x2 %0, %1, %2, %0;" : "+l"(d) : "l"(a), "l"(b));
}
__device__ __forceinline__ ull add2(ull a, ull b) {
    ull r; asm("add.rn.f32x2 %0, %1, %2;" : "=l"(r) : "l"(a), "l"(b)); return r;
}
__device__ __forceinline__ unsigned ld_acq(unsigned* p) {
    unsigned v; asm volatile("ld.acquire.gpu.u32 %0, [%1];" : "=r"(v) : "l"(p) : "memory"); return v;
}
__device__ __forceinline__ void red_rel_add(unsigned* p, unsigned v) {
    asm volatile("red.release.gpu.global.add.u32 [%0], %1;" :: "l"(p), "r"(v) : "memory");
}
__device__ __forceinline__ float tanh_fast(float x) {
    float y; asm("tanh.approx.f32 %0, %1;" : "=f"(y) : "f"(x)); return y;
}
__device__ __forceinline__ float sig_fast(float x) {
    return fmaf(tanh_fast(0.5f * x), 0.5f, 0.5f);
}

// ---------------- reset (counters + all chain states) ----------------
__global__ void k_reset() {
    int i = blockIdx.x*blockDim.x + threadIdx.x;
    if (i < 8*32) g_cnt[i] = 0u;
    if (i < 8192) ((float*)g_stb)[i] = 0.f;
}

// ---------------- mel resnet: one CTA per (b,l) column ----------------
__global__ void k_resnet(const float* __restrict__ mels, const float* __restrict__ w_in,
                         const float* __restrict__ bn0g, const float* __restrict__ bn0b,
                         const float* __restrict__ rc1, const float* __restrict__ rc2,
                         const float* __restrict__ rbn1g, const float* __restrict__ rbn1b,
                         const float* __restrict__ rbn2g, const float* __restrict__ rbn2b,
                         const float* __restrict__ cw, const float* __restrict__ cb,
                         float* __restrict__ aux) {
    int b = blockIdx.x / 50, l = blockIdx.x % 50;
    int o = threadIdx.x;
    __shared__ float mcol[400];
    __shared__ float xs[128], hs[128];
    const float sc = rsqrtf(1.0f + 1e-5f);

    for (int i = o; i < 400; i += 128) {
        int c = i / 5, k = i - c*5;
        mcol[i] = mels[(b*80 + c)*54 + l + k];
    }
    __syncthreads();

    float acc = 0.f;
    const float* wr = w_in + o*400;
    #pragma unroll 8
    for (int i = 0; i < 400; i++) acc += mcol[i] * __ldg(&wr[i]);
    acc = acc*(bn0g[o]*sc) + bn0b[o];
    xs[o] = fmaxf(acc, 0.f);

    for (int ib = 0; ib < 10; ib++) {
        __syncthreads();
        const float* r1 = rc1 + (ib*128 + o)*128;
        float h1 = 0.f;
        #pragma unroll 8
        for (int c = 0; c < 128; c++) h1 += xs[c] * __ldg(&r1[c]);
        h1 = h1*(rbn1g[ib*128+o]*sc) + rbn1b[ib*128+o];
        hs[o] = fmaxf(h1, 0.f);
        __syncthreads();
        const float* r2 = rc2 + (ib*128 + o)*128;
        float h2 = 0.f;
        #pragma unroll 8
        for (int c = 0; c < 128; c++) h2 += hs[c] * __ldg(&r2[c]);
        h2 = h2*(rbn2g[ib*128+o]*sc) + rbn2b[ib*128+o];
        float xn = h2 + xs[o];
        __syncthreads();
        xs[o] = xn;
    }
    __syncthreads();
    float a = 0.f;
    const float* cwr = cw + o*128;
    #pragma unroll 8
    for (int c = 0; c < 128; c++) a += xs[c] * __ldg(&cwr[c]);
    aux[(b*128 + o)*50 + l] = a + cb[o];
}

// ---------------- upsample stage ----------------
__global__ void k_upstage(const float* __restrict__ in, const float* __restrict__ w,
                          float* __restrict__ out, int L, int s, int K, int total) {
    int i = blockIdx.x*256 + threadIdx.x;
    if (i >= total) return;
    int Ls = L*s;
    int row = i / Ls, o = i - row*Ls;
    float acc = 0.f;
    for (int tap = 0; tap < K; tap++) {
        int p = o + tap - s;
        if (p >= 0 && p < Ls) acc += __ldg(&w[tap]) * __ldg(&in[row*L + p/s]);
    }
    out[i] = acc;
}

// ---------------- build padded input matrix for I-layer (M x 128) ----------------
__global__ void k_prep_in(const float* __restrict__ x, float* __restrict__ out) {
    int i = blockIdx.x*256 + threadIdx.x;
    if (i >= M_ROWS*128) return;
    int m = i >> 7, k = i & 127;
    int b = m / T_SZ, t = m - b*T_SZ;
    float v;
    if (k == 0)        v = x[m];
    else if (k <= 80)  v = g_up3[(b*80 + (k-1))*13824 + 512 + t];
    else if (k <= 112) v = g_aux[(b*128 + (k-81))*50 + t/256];
    else               v = 0.f;
    out[i] = v;
}

__global__ void k_pad_iw(const float* __restrict__ iw, float* __restrict__ o) {
    int i = blockIdx.x*256 + threadIdx.x;
    if (i >= 512*128) return;
    int n = i >> 7, k = i & 127;
    o[i] = (k < 113) ? iw[n*113 + k] : 0.f;
}

// ---------------- concat [h(512) | aux slice(32)] -> (M x 544) ----------------
__global__ void k_cat(const float* __restrict__ h, int aoff, float* __restrict__ out) {
    int i = blockIdx.x*256 + threadIdx.x;
    if (i >= M_ROWS*544) return;
    int m = i / 544, j = i - m*544;
    int b = m / T_SZ, t = m - b*T_SZ;
    out[i] = (j < 512) ? h[m*512 + j]
                       : g_aux[(b*128 + aoff + (j-512))*50 + t/256];
}

// ---------------- GEMM: C[m][n] = A[m,:K] . B[n,:K] + bias[n], optional relu ------
// double-buffered smem (ping-pong) + register prefetch; ONE syncthreads per K-tile
__global__ void __launch_bounds__(256) k_gemm(
        const float* __restrict__ A, const float* __restrict__ B,
        const float* __restrict__ bias, float* __restrict__ C,
        int N, int K, int relu) {
    __shared__ float As[2][16][132];
    __shared__ float Bs[2][16][132];
    int tid = threadIdx.x;
    int m0 = blockIdx.y*128, n0 = blockIdx.x*128;
    int tx = tid & 15, ty = tid >> 4;

    int row0 = tid >> 2,          kq0 = (tid & 3) * 4;
    int row1 = (tid + 256) >> 2,  kq1 = ((tid + 256) & 3) * 4;

    ull acc[8][4];
    #pragma unroll
    for (int i = 0; i < 8; i++)
        #pragma unroll
        for (int j = 0; j < 4; j++) acc[i][j] = 0ull;

    {
        float4 va0 = *(const float4*)&A[(size_t)(m0+row0)*K + kq0];
        float4 va1 = *(const float4*)&A[(size_t)(m0+row1)*K + kq1];
        float4 vb0 = *(const float4*)&B[(size_t)(n0+row0)*K + kq0];
        float4 vb1 = *(const float4*)&B[(size_t)(n0+row1)*K + kq1];
        As[0][kq0+0][row0] = va0.x; As[0][kq0+1][row0] = va0.y;
        As[0][kq0+2][row0] = va0.z; As[0][kq0+3][row0] = va0.w;
        As[0][kq1+0][row1] = va1.x; As[0][kq1+1][row1] = va1.y;
        As[0][kq1+2][row1] = va1.z; As[0][kq1+3][row1] = va1.w;
        Bs[0][kq0+0][row0] = vb0.x; Bs[0][kq0+1][row0] = vb0.y;
        Bs[0][kq0+2][row0] = vb0.z; Bs[0][kq0+3][row0] = vb0.w;
        Bs[0][kq1+0][row1] = vb1.x; Bs[0][kq1+1][row1] = vb1.y;
        Bs[0][kq1+2][row1] = vb1.z; Bs[0][kq1+3][row1] = vb1.w;
    }
    __syncthreads();

    int p = 0;
    for (int kb = 0; kb < K; kb += 16) {
        float4 ra0, ra1, rb0, rb1;
        bool more = (kb + 16 < K);
        if (more) {
            ra0 = *(const float4*)&A[(size_t)(m0+row0)*K + kb + 16 + kq0];
            ra1 = *(const float4*)&A[(size_t)(m0+row1)*K + kb + 16 + kq1];
            rb0 = *(const float4*)&B[(size_t)(n0+row0)*K + kb + 16 + kq0];
            rb1 = *(const float4*)&B[(size_t)(n0+row1)*K + kb + 16 + kq1];
        }

        #pragma unroll
        for (int kk = 0; kk < 16; kk++) {
            float a[8];
            *(float4*)&a[0] = *(const float4*)&As[p][kk][ty*8];
            *(float4*)&a[4] = *(const float4*)&As[p][kk][ty*8+4];
            const ull* bp = (const ull*)&Bs[p][kk][tx*8];
            ull b2[4];
            #pragma unroll
            for (int j = 0; j < 4; j++) b2[j] = bp[j];
            #pragma unroll
            for (int i = 0; i < 8; i++) {
                ull ad = pack2(a[i], a[i]);
                #pragma unroll
                for (int j = 0; j < 4; j++) fma2(acc[i][j], ad, b2[j]);
            }
        }

        if (more) {
            int q = p ^ 1;
            As[q][kq0+0][row0] = ra0.x; As[q][kq0+1][row0] = ra0.y;
            As[q][kq0+2][row0] = ra0.z; As[q][kq0+3][row0] = ra0.w;
            As[q][kq1+0][row1] = ra1.x; As[q][kq1+1][row1] = ra1.y;
            As[q][kq1+2][row1] = ra1.z; As[q][kq1+3][row1] = ra1.w;
            Bs[q][kq0+0][row0] = rb0.x; Bs[q][kq0+1][row0] = rb0.y;
            Bs[q][kq0+2][row0] = rb0.z; Bs[q][kq0+3][row0] = rb0.w;
            Bs[q][kq1+0][row1] = rb1.x; Bs[q][kq1+1][row1] = rb1.y;
            Bs[q][kq1+2][row1] = rb1.z; Bs[q][kq1+3][row1] = rb1.w;
            __syncthreads();
            p = q;
        }
    }

    #pragma unroll
    for (int i = 0; i < 8; i++) {
        int m = m0 + ty*8 + i;
        float* cp = &C[(size_t)m*N + n0 + tx*8];
        #pragma unroll
        for (int j = 0; j < 4; j++) {
            float2 v = unpack2(acc[i][j]);
            float2 bb = *(const float2*)&bias[n0 + tx*8 + 2*j];
            v.x += bb.x; v.y += bb.y;
            if (relu) { v.x = fmaxf(v.x, 0.f); v.y = fmaxf(v.y, 0.f); }
            *(float2*)&cp[2*j] = v;
        }
    }
}

// ---------------- batch-split persistent GRU (16 CTAs x 512 threads per chain) ----
// 4 independent chains x 16 CTAs x 16 warps; warp owns 2 adjacent h-indices
// (32 h per CTA). Same proven epoch structure as R12: smem staging of 2KB h
// vector, tid0 polls own 16-arrival chain counter, __syncthreads broadcast,
// red.release arrive, prefetch under the wait.
__global__ void __launch_bounds__(512,1) k_gru_b(
        const float* __restrict__ whh, const float* __restrict__ bhh,
        const float* __restrict__ xp, float* __restrict__ hio,
        float* __restrict__ st, unsigned* __restrict__ cnt) {
    const int lane = threadIdx.x & 31;
    const int wid = threadIdx.x >> 5;         // 0..15
    const int tid = threadIdx.x;
    const int b = blockIdx.x >> 4;            // batch chain 0..3
    const int cic = blockIdx.x & 15;          // cta within chain
    const int h0 = cic*32 + wid*2;            // this warp's h-pair

    float* stb = st + b*1024;                 // [2][512]
    unsigned* cb = cnt + b*32;                // own 128B line

    __shared__ __align__(16) float s_h[512];

    // weights packed (h0,h1): wp[g][j128*4+q] for j = lane*4+q + j128*128
    ull wp[3][16];
    #pragma unroll
    for (int g = 0; g < 3; g++) {
        const float* w0 = whh + (size_t)(g*512 + h0)*512;
        const float* w1 = w0 + 512;
        #pragma unroll
        for (int j128 = 0; j128 < 4; j128++)
            #pragma unroll
            for (int q = 0; q < 4; q++) {
                int j = lane*4 + q + j128*128;
                wp[g][j128*4+q] = pack2(__ldg(&w0[j]), __ldg(&w1[j]));
            }
    }
    const float br0 = __ldg(&bhh[h0]),      br1 = __ldg(&bhh[h0+1]);
    const float bz0 = __ldg(&bhh[512+h0]),  bz1 = __ldg(&bhh[512+h0+1]);
    const float bn0 = __ldg(&bhh[1024+h0]), bn1 = __ldg(&bhh[1024+h0+1]);

    float2 hprev = make_float2(0.f, 0.f);
    float2 xr, xz, xn, hres;
    if (lane == 0) {                          // preload t=0 inputs
        size_t xb = (size_t)(b*T_SZ + 0)*1536 + h0;
        xr   = *(const float2*)&xp[xb];
        xz   = *(const float2*)&xp[xb + 512];
        xn   = *(const float2*)&xp[xb + 1024];
        hres = *(const float2*)&hio[(size_t)(b*T_SZ + 0)*512 + h0];
    }

    for (int t = 0; t < T_SZ; t++) {
        // stage 2KB h vector: threads 0-127 load one float4 each
        if (tid < 128)
            *(float4*)&s_h[tid*4] = __ldcg((const float4*)(stb + (t & 1)*512) + tid);
        __syncthreads();

        // matvec: acc[g] packs (sum_h0, sum_h1)
        ull acc[3] = {0ull, 0ull, 0ull};
        #pragma unroll
        for (int j128 = 0; j128 < 4; j128++) {
            float4 hv = *(const float4*)&s_h[lane*4 + j128*128];
            #pragma unroll
            for (int q = 0; q < 4; q++) {
                float hq = (q == 0) ? hv.x : (q == 1) ? hv.y : (q == 2) ? hv.z : hv.w;
                ull hd = dup2(hq);
                #pragma unroll
                for (int g = 0; g < 3; g++) fma2(acc[g], wp[g][j128*4+q], hd);
            }
        }
        #pragma unroll
        for (int g = 0; g < 3; g++)
            #pragma unroll
            for (int off = 16; off > 0; off >>= 1)
                acc[g] = add2(acc[g], __shfl_xor_sync(0xffffffffu, acc[g], off));

        float2 hnew = hprev;
        if (lane == 0) {
            float2 pr = unpack2(acc[0]);
            float2 pz = unpack2(acc[1]);
            float2 pn = unpack2(acc[2]);
            float r0 = sig_fast(xr.x + pr.x + br0);
            float z0 = sig_fast(xz.x + pz.x + bz0);
            float n0 = tanh_fast(xn.x + r0*(pn.x + bn0));
            float r1 = sig_fast(xr.y + pr.y + br1);
            float z1 = sig_fast(xz.y + pz.y + bz1);
            float n1 = tanh_fast(xn.y + r1*(pn.y + bn1));
            hnew.x = (1.f - z0)*n0 + z0*hprev.x;
            hnew.y = (1.f - z1)*n1 + z1*hprev.y;
            hprev = hnew;
            *(float2*)&stb[((t+1) & 1)*512 + h0] = hnew;
        }

        __syncthreads();                      // all warps' state stores done
        if (tid == 0) red_rel_add(cb, 1u);

        // off-critical-path: residual output + next-step prefetch
        if (lane == 0) {
            *(float2*)&hio[(size_t)(b*T_SZ + t)*512 + h0] =
                make_float2(hres.x + hnew.x, hres.y + hnew.y);
            if (t + 1 < T_SZ) {
                size_t xb = (size_t)(b*T_SZ + t + 1)*1536 + h0;
                xr   = *(const float2*)&xp[xb];
                xz   = *(const float2*)&xp[xb + 512];
                xn   = *(const float2*)&xp[xb + 1024];
                hres = *(const float2*)&hio[(size_t)(b*T_SZ + t + 1)*512 + h0];
            }
        }

        if (t + 1 < T_SZ) {
            if (tid == 0) {                   // single poller; 16-arrival counter
                unsigned tgt = (unsigned)(t + 1) * (unsigned)CCTA;
                while (ld_acq(cb) < tgt) {}
            }
            __syncthreads();
        }
    }
}

// ---------------- host ----------------
static float* sym_addr(const void* s) {
    void* p = nullptr;
    cudaGetSymbolAddress(&p, s);
    return (float*)p;
}

extern "C" void kernel_launch(void* const* d_in, const int* in_sizes, int n_in,
                              void* d_out, int out_size) {
    const float* x        = (const float*)d_in[0];
    const float* mels     = (const float*)d_in[1];
    const float* conv_in_w= (const float*)d_in[2];
    const float* bn0_g    = (const float*)d_in[3];
    const float* bn0_b    = (const float*)d_in[4];
    const float* res_c1   = (const float*)d_in[5];
    const float* res_c2   = (const float*)d_in[6];
    const float* rbn1_g   = (const float*)d_in[7];
    const float* rbn1_b   = (const float*)d_in[8];
    const float* rbn2_g   = (const float*)d_in[9];
    const float* rbn2_b   = (const float*)d_in[10];
    const float* conv_ow  = (const float*)d_in[11];
    const float* conv_ob  = (const float*)d_in[12];
    const float* up_w0    = (const float*)d_in[13];
    const float* up_w1    = (const float*)d_in[14];
    const float* up_w2    = (const float*)d_in[15];
    const float* I_w      = (const float*)d_in[16];
    const float* I_b      = (const float*)d_in[17];
    const float* r1_wih   = (const float*)d_in[18];
    const float* r1_whh   = (const float*)d_in[19];
    const float* r1_bih   = (const float*)d_in[20];
    const float* r1_bhh   = (const float*)d_in[21];
    const float* r2_wih   = (const float*)d_in[22];
    const float* r2_whh   = (const float*)d_in[23];
    const float* r2_bih   = (const float*)d_in[24];
    const float* r2_bhh   = (const float*)d_in[25];
    const float* fc1_w    = (const float*)d_in[26];
    const float* fc1_b    = (const float*)d_in[27];
    const float* fc2_w    = (const float*)d_in[28];
    const float* fc2_b    = (const float*)d_in[29];
    const float* fc3_w    = (const float*)d_in[30];
    const float* fc3_b    = (const float*)d_in[31];
    float* out = (float*)d_out;

    float* p_aux = sym_addr(g_aux);
    float* p_up1 = sym_addr(g_up1);
    float* p_up2 = sym_addr(g_up2);
    float* p_up3 = sym_addr(g_up3);
    float* p_in0 = sym_addr(g_in0);
    float* p_iw  = sym_addr(g_iw);
    float* p_h   = sym_addr(g_h);
    float* p_xp  = sym_addr(g_xp);
    float* p_cat = sym_addr(g_cat);
    float* p_f1  = sym_addr(g_f1);
    float* p_f2  = sym_addr(g_f2);
    float* p_st  = sym_addr(g_stb);
    unsigned* p_cnt = (unsigned*)sym_addr(g_cnt);

    // 1. aux (mel resnet) and upsample chain
    k_resnet<<<200, 128>>>(mels, conv_in_w, bn0_g, bn0_b, res_c1, res_c2,
                           rbn1_g, rbn1_b, rbn2_g, rbn2_b, conv_ow, conv_ob, p_aux);
    k_upstage<<<(4*80*216 + 255)/256, 256>>>(mels, up_w0, p_up1, 54, 4, 9, 4*80*216);
    k_upstage<<<(4*80*1728 + 255)/256, 256>>>(p_up1, up_w1, p_up2, 216, 8, 17, 4*80*1728);
    k_upstage<<<(4*80*13824 + 255)/256, 256>>>(p_up2, up_w2, p_up3, 1728, 8, 17, 4*80*13824);

    // 2. I layer: h0 = [x | m_up | a1] @ I_w.T + I_b
    k_pad_iw<<<(512*128 + 255)/256, 256>>>(I_w, p_iw);
    k_prep_in<<<(M_ROWS*128)/256, 256>>>(x, p_in0);
    k_gemm<<<dim3(4, 400), 256>>>(p_in0, p_iw, I_b, p_h, 512, 128, 0);

    // 3. reset chain states + counters (both phases)
    k_reset<<<32, 256>>>();

    // 4. GRU1: xp1 GEMM then 4 concurrent batch chains (h = ys1 + h0)
    k_gemm<<<dim3(12, 400), 256>>>(p_h, r1_wih, r1_bih, p_xp, 1536, 512, 0);
    k_gru_b<<<4*CCTA, 512>>>(r1_whh, r1_bhh, p_xp, p_h, p_st, p_cnt);

    // 5. GRU2: cat(h, a2) -> xp2 GEMM -> 4 concurrent batch chains
    k_cat<<<(M_ROWS*544 + 255)/256, 256>>>(p_h, 32, p_cat);
    k_gemm<<<dim3(12, 400), 256>>>(p_cat, r2_wih, r2_bih, p_xp, 1536, 544, 0);
    k_gru_b<<<4*CCTA, 512>>>(r2_whh, r2_bhh, p_xp, p_h, p_st + 4*1024, p_cnt + 4*32);

    // 6. fc1 / fc2 / fc3
    k_cat<<<(M_ROWS*544 + 255)/256, 256>>>(p_h, 64, p_cat);
    k_gemm<<<dim3(4, 400), 256>>>(p_cat, fc1_w, fc1_b, p_f1, 512, 544, 1);
    k_cat<<<(M_ROWS*544 + 255)/256, 256>>>(p_f1, 96, p_cat);
    k_gemm<<<dim3(4, 400), 256>>>(p_cat, fc2_w, fc2_b, p_f2, 512, 544, 1);
    k_gemm<<<dim3(8, 400), 256>>>(p_f2, fc3_w, fc3_b, out, 1024, 512, 0);
}

// round 16
// speedup vs baseline: 1.2092x; 1.2092x over previous
#include <cuda_runtime.h>
#include <cuda_bf16.h>
#include <math.h>

typedef unsigned long long ull;

#define B_SZ 4
#define T_SZ 12800
#define M_ROWS (B_SZ*T_SZ)   // 51200
#define CCTA 32              // CTAs per batch chain

// ---------------- static device scratch (no allocation anywhere) ----------------
__device__ __align__(256) float g_aux[4*128*50];
__device__ __align__(256) float g_up1[4*80*216];
__device__ __align__(256) float g_up2[4*80*1728];
__device__ __align__(256) float g_up3[4*80*13824];
__device__ __align__(256) float g_in0[M_ROWS*128];
__device__ __align__(256) float g_iw[512*128];
__device__ __align__(256) float g_h[M_ROWS*512];
__device__ __align__(256) float g_xp[M_ROWS*1536];
__device__ __align__(256) float g_cat[M_ROWS*544];
__device__ __align__(256) float g_f1[M_ROWS*512];
__device__ __align__(256) float g_f2[M_ROWS*512];
// per-phase, per-batch double-buffered h state: [(phase*4+b)][buf][512]
__device__ __align__(256) float g_stb[8][2][512];
// per-phase, per-batch barrier counters, one 128B line each
__device__ __align__(128) unsigned g_cnt[8*32];

// ---------------- f32x2 / sync / math helpers ----------------
__device__ __forceinline__ ull pack2(float x, float y) {
    ull r; asm("mov.b64 %0, {%1,%2};" : "=l"(r) : "f"(x), "f"(y)); return r;
}
__device__ __forceinline__ ull dup2(float x) {
    ull r; unsigned u = __float_as_uint(x);
    asm("mov.b64 %0, {%1,%1};" : "=l"(r) : "r"(u)); return r;
}
__device__ __forceinline__ float2 unpack2(ull v) {
    float2 f; asm("mov.b64 {%0,%1}, %2;" : "=f"(f.x), "=f"(f.y) : "l"(v)); return f;
}
__device__ __forceinline__ void fma2(ull& d, ull a, ull b) {
    asm("fma.rn.f32x2 %0, %1, %2, %0;" : "+l"(d) : "l"(a), "l"(b));
}
__device__ __forceinline__ ull add2(ull a, ull b) {
    ull r; asm("add.rn.f32x2 %0, %1, %2;" : "=l"(r) : "l"(a), "l"(b)); return r;
}
__device__ __forceinline__ unsigned ld_acq(unsigned* p) {
    unsigned v; asm volatile("ld.acquire.gpu.u32 %0, [%1];" : "=r"(v) : "l"(p) : "memory"); return v;
}
__device__ __forceinline__ void red_rel_add(unsigned* p, unsigned v) {
    asm volatile("red.release.gpu.global.add.u32 [%0], %1;" :: "l"(p), "r"(v) : "memory");
}
__device__ __forceinline__ float tanh_fast(float x) {
    float y; asm("tanh.approx.f32 %0, %1;" : "=f"(y) : "f"(x)); return y;
}
__device__ __forceinline__ float sig_fast(float x) {
    return fmaf(tanh_fast(0.5f * x), 0.5f, 0.5f);
}

// ---------------- reset (counters + all chain states) ----------------
__global__ void k_reset() {
    int i = blockIdx.x*blockDim.x + threadIdx.x;
    if (i < 8*32) g_cnt[i] = 0u;
    if (i < 8192) ((float*)g_stb)[i] = 0.f;
}

// ---------------- mel resnet: one CTA per (b,l) column ----------------
__global__ void k_resnet(const float* __restrict__ mels, const float* __restrict__ w_in,
                         const float* __restrict__ bn0g, const float* __restrict__ bn0b,
                         const float* __restrict__ rc1, const float* __restrict__ rc2,
                         const float* __restrict__ rbn1g, const float* __restrict__ rbn1b,
                         const float* __restrict__ rbn2g, const float* __restrict__ rbn2b,
                         const float* __restrict__ cw, const float* __restrict__ cb,
                         float* __restrict__ aux) {
    int b = blockIdx.x / 50, l = blockIdx.x % 50;
    int o = threadIdx.x;
    __shared__ float mcol[400];
    __shared__ float xs[128], hs[128];
    const float sc = rsqrtf(1.0f + 1e-5f);

    for (int i = o; i < 400; i += 128) {
        int c = i / 5, k = i - c*5;
        mcol[i] = mels[(b*80 + c)*54 + l + k];
    }
    __syncthreads();

    float acc = 0.f;
    const float* wr = w_in + o*400;
    #pragma unroll 8
    for (int i = 0; i < 400; i++) acc += mcol[i] * __ldg(&wr[i]);
    acc = acc*(bn0g[o]*sc) + bn0b[o];
    xs[o] = fmaxf(acc, 0.f);

    for (int ib = 0; ib < 10; ib++) {
        __syncthreads();
        const float* r1 = rc1 + (ib*128 + o)*128;
        float h1 = 0.f;
        #pragma unroll 8
        for (int c = 0; c < 128; c++) h1 += xs[c] * __ldg(&r1[c]);
        h1 = h1*(rbn1g[ib*128+o]*sc) + rbn1b[ib*128+o];
        hs[o] = fmaxf(h1, 0.f);
        __syncthreads();
        const float* r2 = rc2 + (ib*128 + o)*128;
        float h2 = 0.f;
        #pragma unroll 8
        for (int c = 0; c < 128; c++) h2 += hs[c] * __ldg(&r2[c]);
        h2 = h2*(rbn2g[ib*128+o]*sc) + rbn2b[ib*128+o];
        float xn = h2 + xs[o];
        __syncthreads();
        xs[o] = xn;
    }
    __syncthreads();
    float a = 0.f;
    const float* cwr = cw + o*128;
    #pragma unroll 8
    for (int c = 0; c < 128; c++) a += xs[c] * __ldg(&cwr[c]);
    aux[(b*128 + o)*50 + l] = a + cb[o];
}

// ---------------- upsample stage ----------------
__global__ void k_upstage(const float* __restrict__ in, const float* __restrict__ w,
                          float* __restrict__ out, int L, int s, int K, int total) {
    int i = blockIdx.x*256 + threadIdx.x;
    if (i >= total) return;
    int Ls = L*s;
    int row = i / Ls, o = i - row*Ls;
    float acc = 0.f;
    for (int tap = 0; tap < K; tap++) {
        int p = o + tap - s;
        if (p >= 0 && p < Ls) acc += __ldg(&w[tap]) * __ldg(&in[row*L + p/s]);
    }
    out[i] = acc;
}

// ---------------- build padded input matrix for I-layer (M x 128) ----------------
__global__ void k_prep_in(const float* __restrict__ x, float* __restrict__ out) {
    int i = blockIdx.x*256 + threadIdx.x;
    if (i >= M_ROWS*128) return;
    int m = i >> 7, k = i & 127;
    int b = m / T_SZ, t = m - b*T_SZ;
    float v;
    if (k == 0)        v = x[m];
    else if (k <= 80)  v = g_up3[(b*80 + (k-1))*13824 + 512 + t];
    else if (k <= 112) v = g_aux[(b*128 + (k-81))*50 + t/256];
    else               v = 0.f;
    out[i] = v;
}

__global__ void k_pad_iw(const float* __restrict__ iw, float* __restrict__ o) {
    int i = blockIdx.x*256 + threadIdx.x;
    if (i >= 512*128) return;
    int n = i >> 7, k = i & 127;
    o[i] = (k < 113) ? iw[n*113 + k] : 0.f;
}

// ---------------- concat [h(512) | aux slice(32)] -> (M x 544) ----------------
__global__ void k_cat(const float* __restrict__ h, int aoff, float* __restrict__ out) {
    int i = blockIdx.x*256 + threadIdx.x;
    if (i >= M_ROWS*544) return;
    int m = i / 544, j = i - m*544;
    int b = m / T_SZ, t = m - b*T_SZ;
    out[i] = (j < 512) ? h[m*512 + j]
                       : g_aux[(b*128 + aoff + (j-512))*50 + t/256];
}

// ---------------- GEMM: C[m][n] = A[m,:K] . B[n,:K] + bias[n], optional relu ------
// Double-buffered DYNAMIC smem; A stored PRE-DUPLICATED as f32x2 pairs so the
// inner loop has zero pack movs (pure LDS + fma2). One syncthreads per K-tile.
// smem: As ull[2][16][128] (32KB) + Bs float[2][16][132] (16.9KB) = 49.7KB.
__global__ void __launch_bounds__(256) k_gemm(
        const float* __restrict__ A, const float* __restrict__ B,
        const float* __restrict__ bias, float* __restrict__ C,
        int N, int K, int relu) {
    extern __shared__ char smem_raw[];
    ull   (*As)[16][128] = (ull(*)[16][128])smem_raw;
    float (*Bs)[16][132] = (float(*)[16][132])(smem_raw + 2*16*128*sizeof(ull));

    int tid = threadIdx.x;
    int m0 = blockIdx.y*128, n0 = blockIdx.x*128;
    int tx = tid & 15, ty = tid >> 4;

    int row0 = tid >> 2,          kq0 = (tid & 3) * 4;
    int row1 = (tid + 256) >> 2,  kq1 = ((tid + 256) & 3) * 4;

    ull acc[8][4];
    #pragma unroll
    for (int i = 0; i < 8; i++)
        #pragma unroll
        for (int j = 0; j < 4; j++) acc[i][j] = 0ull;

    {
        float4 va0 = *(const float4*)&A[(size_t)(m0+row0)*K + kq0];
        float4 va1 = *(const float4*)&A[(size_t)(m0+row1)*K + kq1];
        float4 vb0 = *(const float4*)&B[(size_t)(n0+row0)*K + kq0];
        float4 vb1 = *(const float4*)&B[(size_t)(n0+row1)*K + kq1];
        As[0][kq0+0][row0] = dup2(va0.x); As[0][kq0+1][row0] = dup2(va0.y);
        As[0][kq0+2][row0] = dup2(va0.z); As[0][kq0+3][row0] = dup2(va0.w);
        As[0][kq1+0][row1] = dup2(va1.x); As[0][kq1+1][row1] = dup2(va1.y);
        As[0][kq1+2][row1] = dup2(va1.z); As[0][kq1+3][row1] = dup2(va1.w);
        Bs[0][kq0+0][row0] = vb0.x; Bs[0][kq0+1][row0] = vb0.y;
        Bs[0][kq0+2][row0] = vb0.z; Bs[0][kq0+3][row0] = vb0.w;
        Bs[0][kq1+0][row1] = vb1.x; Bs[0][kq1+1][row1] = vb1.y;
        Bs[0][kq1+2][row1] = vb1.z; Bs[0][kq1+3][row1] = vb1.w;
    }
    __syncthreads();

    int p = 0;
    for (int kb = 0; kb < K; kb += 16) {
        float4 ra0, ra1, rb0, rb1;
        bool more = (kb + 16 < K);
        if (more) {
            ra0 = *(const float4*)&A[(size_t)(m0+row0)*K + kb + 16 + kq0];
            ra1 = *(const float4*)&A[(size_t)(m0+row1)*K + kb + 16 + kq1];
            rb0 = *(const float4*)&B[(size_t)(n0+row0)*K + kb + 16 + kq0];
            rb1 = *(const float4*)&B[(size_t)(n0+row1)*K + kb + 16 + kq1];
        }

        // inner loop: pure LDS + fma2 (A already duplicated in smem)
        #pragma unroll
        for (int kk = 0; kk < 16; kk++) {
            const ull* ap = &As[p][kk][ty*8];
            ull a2[8];
            #pragma unroll
            for (int i = 0; i < 8; i++) a2[i] = ap[i];
            const ull* bp = (const ull*)&Bs[p][kk][tx*8];
            ull b2[4];
            #pragma unroll
            for (int j = 0; j < 4; j++) b2[j] = bp[j];
            #pragma unroll
            for (int i = 0; i < 8; i++)
                #pragma unroll
                for (int j = 0; j < 4; j++) fma2(acc[i][j], a2[i], b2[j]);
        }

        if (more) {
            int q = p ^ 1;
            As[q][kq0+0][row0] = dup2(ra0.x); As[q][kq0+1][row0] = dup2(ra0.y);
            As[q][kq0+2][row0] = dup2(ra0.z); As[q][kq0+3][row0] = dup2(ra0.w);
            As[q][kq1+0][row1] = dup2(ra1.x); As[q][kq1+1][row1] = dup2(ra1.y);
            As[q][kq1+2][row1] = dup2(ra1.z); As[q][kq1+3][row1] = dup2(ra1.w);
            Bs[q][kq0+0][row0] = rb0.x; Bs[q][kq0+1][row0] = rb0.y;
            Bs[q][kq0+2][row0] = rb0.z; Bs[q][kq0+3][row0] = rb0.w;
            Bs[q][kq1+0][row1] = rb1.x; Bs[q][kq1+1][row1] = rb1.y;
            Bs[q][kq1+2][row1] = rb1.z; Bs[q][kq1+3][row1] = rb1.w;
            __syncthreads();
            p = q;
        }
    }

    #pragma unroll
    for (int i = 0; i < 8; i++) {
        int m = m0 + ty*8 + i;
        float* cp = &C[(size_t)m*N + n0 + tx*8];
        #pragma unroll
        for (int j = 0; j < 4; j++) {
            float2 v = unpack2(acc[i][j]);
            float2 bb = *(const float2*)&bias[n0 + tx*8 + 2*j];
            v.x += bb.x; v.y += bb.y;
            if (relu) { v.x = fmaxf(v.x, 0.f); v.y = fmaxf(v.y, 0.f); }
            *(float2*)&cp[2*j] = v;
        }
    }
}
static const int GEMM_SMEM = 2*16*128*8 + 2*16*132*4;   // 49664 bytes

// ---------------- batch-split persistent GRU (R14 proven — frozen) ----------------
// 4 independent chains x 32 CTAs x 8 warps; warp owns 2 adjacent h-indices.
// smem staging of 2KB h vector; tid0 polls own 32-arrival chain counter;
// __syncthreads broadcast; red.release arrive; prefetch under the wait.
__global__ void __launch_bounds__(256,1) k_gru_b(
        const float* __restrict__ whh, const float* __restrict__ bhh,
        const float* __restrict__ xp, float* __restrict__ hio,
        float* __restrict__ st, unsigned* __restrict__ cnt) {
    const int lane = threadIdx.x & 31;
    const int wid = threadIdx.x >> 5;         // 0..7
    const int tid = threadIdx.x;
    const int b = blockIdx.x >> 5;            // batch chain 0..3
    const int cic = blockIdx.x & 31;          // cta within chain
    const int h0 = cic*16 + wid*2;            // this warp's h-pair

    float* stb = st + b*1024;                 // [2][512]
    unsigned* cb = cnt + b*32;                // own 128B line

    __shared__ __align__(16) float s_h[512];

    // weights packed (h0,h1): wp[g][j128*4+q] for j = lane*4+q + j128*128
    ull wp[3][16];
    #pragma unroll
    for (int g = 0; g < 3; g++) {
        const float* w0 = whh + (size_t)(g*512 + h0)*512;
        const float* w1 = w0 + 512;
        #pragma unroll
        for (int j128 = 0; j128 < 4; j128++)
            #pragma unroll
            for (int q = 0; q < 4; q++) {
                int j = lane*4 + q + j128*128;
                wp[g][j128*4+q] = pack2(__ldg(&w0[j]), __ldg(&w1[j]));
            }
    }
    const float br0 = __ldg(&bhh[h0]),      br1 = __ldg(&bhh[h0+1]);
    const float bz0 = __ldg(&bhh[512+h0]),  bz1 = __ldg(&bhh[512+h0+1]);
    const float bn0 = __ldg(&bhh[1024+h0]), bn1 = __ldg(&bhh[1024+h0+1]);

    float2 hprev = make_float2(0.f, 0.f);
    float2 xr, xz, xn, hres;
    if (lane == 0) {                          // preload t=0 inputs
        size_t xb = (size_t)(b*T_SZ + 0)*1536 + h0;
        xr   = *(const float2*)&xp[xb];
        xz   = *(const float2*)&xp[xb + 512];
        xn   = *(const float2*)&xp[xb + 1024];
        hres = *(const float2*)&hio[(size_t)(b*T_SZ + 0)*512 + h0];
    }

    for (int t = 0; t < T_SZ; t++) {
        // stage 2KB h vector: threads 0-127 load one float4 each
        if (tid < 128)
            *(float4*)&s_h[tid*4] = __ldcg((const float4*)(stb + (t & 1)*512) + tid);
        __syncthreads();

        // matvec: acc[g] packs (sum_h0, sum_h1)
        ull acc[3] = {0ull, 0ull, 0ull};
        #pragma unroll
        for (int j128 = 0; j128 < 4; j128++) {
            float4 hv = *(const float4*)&s_h[lane*4 + j128*128];
            #pragma unroll
            for (int q = 0; q < 4; q++) {
                float hq = (q == 0) ? hv.x : (q == 1) ? hv.y : (q == 2) ? hv.z : hv.w;
                ull hd = dup2(hq);
                #pragma unroll
                for (int g = 0; g < 3; g++) fma2(acc[g], wp[g][j128*4+q], hd);
            }
        }
        #pragma unroll
        for (int g = 0; g < 3; g++)
            #pragma unroll
            for (int off = 16; off > 0; off >>= 1)
                acc[g] = add2(acc[g], __shfl_xor_sync(0xffffffffu, acc[g], off));

        float2 hnew = hprev;
        if (lane == 0) {
            float2 pr = unpack2(acc[0]);
            float2 pz = unpack2(acc[1]);
            float2 pn = unpack2(acc[2]);
            float r0 = sig_fast(xr.x + pr.x + br0);
            float z0 = sig_fast(xz.x + pz.x + bz0);
            float n0 = tanh_fast(xn.x + r0*(pn.x + bn0));
            float r1 = sig_fast(xr.y + pr.y + br1);
            float z1 = sig_fast(xz.y + pz.y + bz1);
            float n1 = tanh_fast(xn.y + r1*(pn.y + bn1));
            hnew.x = (1.f - z0)*n0 + z0*hprev.x;
            hnew.y = (1.f - z1)*n1 + z1*hprev.y;
            hprev = hnew;
            *(float2*)&stb[((t+1) & 1)*512 + h0] = hnew;
        }

        __syncthreads();                      // all warps' state stores done
        if (tid == 0) red_rel_add(cb, 1u);

        // off-critical-path: residual output + next-step prefetch
        if (lane == 0) {
            *(float2*)&hio[(size_t)(b*T_SZ + t)*512 + h0] =
                make_float2(hres.x + hnew.x, hres.y + hnew.y);
            if (t + 1 < T_SZ) {
                size_t xb = (size_t)(b*T_SZ + t + 1)*1536 + h0;
                xr   = *(const float2*)&xp[xb];
                xz   = *(const float2*)&xp[xb + 512];
                xn   = *(const float2*)&xp[xb + 1024];
                hres = *(const float2*)&hio[(size_t)(b*T_SZ + t + 1)*512 + h0];
            }
        }

        if (t + 1 < T_SZ) {
            if (tid == 0) {                   // single poller; 32-arrival counter
                unsigned tgt = (unsigned)(t + 1) * (unsigned)CCTA;
                while (ld_acq(cb) < tgt) {}
            }
            __syncthreads();
        }
    }
}

// ---------------- host ----------------
static float* sym_addr(const void* s) {
    void* p = nullptr;
    cudaGetSymbolAddress(&p, s);
    return (float*)p;
}

extern "C" void kernel_launch(void* const* d_in, const int* in_sizes, int n_in,
                              void* d_out, int out_size) {
    const float* x        = (const float*)d_in[0];
    const float* mels     = (const float*)d_in[1];
    const float* conv_in_w= (const float*)d_in[2];
    const float* bn0_g    = (const float*)d_in[3];
    const float* bn0_b    = (const float*)d_in[4];
    const float* res_c1   = (const float*)d_in[5];
    const float* res_c2   = (const float*)d_in[6];
    const float* rbn1_g   = (const float*)d_in[7];
    const float* rbn1_b   = (const float*)d_in[8];
    const float* rbn2_g   = (const float*)d_in[9];
    const float* rbn2_b   = (const float*)d_in[10];
    const float* conv_ow  = (const float*)d_in[11];
    const float* conv_ob  = (const float*)d_in[12];
    const float* up_w0    = (const float*)d_in[13];
    const float* up_w1    = (const float*)d_in[14];
    const float* up_w2    = (const float*)d_in[15];
    const float* I_w      = (const float*)d_in[16];
    const float* I_b      = (const float*)d_in[17];
    const float* r1_wih   = (const float*)d_in[18];
    const float* r1_whh   = (const float*)d_in[19];
    const float* r1_bih   = (const float*)d_in[20];
    const float* r1_bhh   = (const float*)d_in[21];
    const float* r2_wih   = (const float*)d_in[22];
    const float* r2_whh   = (const float*)d_in[23];
    const float* r2_bih   = (const float*)d_in[24];
    const float* r2_bhh   = (const float*)d_in[25];
    const float* fc1_w    = (const float*)d_in[26];
    const float* fc1_b    = (const float*)d_in[27];
    const float* fc2_w    = (const float*)d_in[28];
    const float* fc2_b    = (const float*)d_in[29];
    const float* fc3_w    = (const float*)d_in[30];
    const float* fc3_b    = (const float*)d_in[31];
    float* out = (float*)d_out;

    float* p_aux = sym_addr(g_aux);
    float* p_up1 = sym_addr(g_up1);
    float* p_up2 = sym_addr(g_up2);
    float* p_up3 = sym_addr(g_up3);
    float* p_in0 = sym_addr(g_in0);
    float* p_iw  = sym_addr(g_iw);
    float* p_h   = sym_addr(g_h);
    float* p_xp  = sym_addr(g_xp);
    float* p_cat = sym_addr(g_cat);
    float* p_f1  = sym_addr(g_f1);
    float* p_f2  = sym_addr(g_f2);
    float* p_st  = sym_addr(g_stb);
    unsigned* p_cnt = (unsigned*)sym_addr(g_cnt);

    // allow >48KB dynamic smem for k_gemm (host-side attribute, capture-legal)
    cudaFuncSetAttribute(k_gemm, cudaFuncAttributeMaxDynamicSharedMemorySize,
                         GEMM_SMEM);

    // 1. aux (mel resnet) and upsample chain
    k_resnet<<<200, 128>>>(mels, conv_in_w, bn0_g, bn0_b, res_c1, res_c2,
                           rbn1_g, rbn1_b, rbn2_g, rbn2_b, conv_ow, conv_ob, p_aux);
    k_upstage<<<(4*80*216 + 255)/256, 256>>>(mels, up_w0, p_up1, 54, 4, 9, 4*80*216);
    k_upstage<<<(4*80*1728 + 255)/256, 256>>>(p_up1, up_w1, p_up2, 216, 8, 17, 4*80*1728);
    k_upstage<<<(4*80*13824 + 255)/256, 256>>>(p_up2, up_w2, p_up3, 1728, 8, 17, 4*80*13824);

    // 2. I layer: h0 = [x | m_up | a1] @ I_w.T + I_b
    k_pad_iw<<<(512*128 + 255)/256, 256>>>(I_w, p_iw);
    k_prep_in<<<(M_ROWS*128)/256, 256>>>(x, p_in0);
    k_gemm<<<dim3(4, 400), 256, GEMM_SMEM>>>(p_in0, p_iw, I_b, p_h, 512, 128, 0);

    // 3. reset chain states + counters (both phases)
    k_reset<<<32, 256>>>();

    // 4. GRU1: xp1 GEMM then 4 concurrent batch chains (h = ys1 + h0)
    k_gemm<<<dim3(12, 400), 256, GEMM_SMEM>>>(p_h, r1_wih, r1_bih, p_xp, 1536, 512, 0);
    k_gru_b<<<4*CCTA, 256>>>(r1_whh, r1_bhh, p_xp, p_h, p_st, p_cnt);

    // 5. GRU2: cat(h, a2) -> xp2 GEMM -> 4 concurrent batch chains
    k_cat<<<(M_ROWS*544 + 255)/256, 256>>>(p_h, 32, p_cat);
    k_gemm<<<dim3(12, 400), 256, GEMM_SMEM>>>(p_cat, r2_wih, r2_bih, p_xp, 1536, 544, 0);
    k_gru_b<<<4*CCTA, 256>>>(r2_whh, r2_bhh, p_xp, p_h, p_st + 4*1024, p_cnt + 4*32);

    // 6. fc1 / fc2 / fc3
    k_cat<<<(M_ROWS*544 + 255)/256, 256>>>(p_h, 64, p_cat);
    k_gemm<<<dim3(4, 400), 256, GEMM_SMEM>>>(p_cat, fc1_w, fc1_b, p_f1, 512, 544, 1);
    k_cat<<<(M_ROWS*544 + 255)/256, 256>>>(p_f1, 96, p_cat);
    k_gemm<<<dim3(4, 400), 256, GEMM_SMEM>>>(p_cat, fc2_w, fc2_b, p_f2, 512, 544, 1);
    k_gemm<<<dim3(8, 400), 256, GEMM_SMEM>>>(p_f2, fc3_w, fc3_b, out, 1024, 512, 0);
}

// round 17
// speedup vs baseline: 1.2671x; 1.0479x over previous
#include <cuda_runtime.h>
#include <cuda_bf16.h>
#include <math.h>

typedef unsigned long long ull;

#define B_SZ 4
#define T_SZ 12800
#define M_ROWS (B_SZ*T_SZ)   // 51200
#define CCTA 32              // CTAs per batch chain

// ---------------- static device scratch (no allocation anywhere) ----------------
__device__ __align__(256) float g_aux[4*128*50];
__device__ __align__(256) float g_up1[4*80*216];
__device__ __align__(256) float g_up2[4*80*1728];
__device__ __align__(256) float g_up3[4*80*13824];
__device__ __align__(256) float g_in0[M_ROWS*128];
__device__ __align__(256) float g_iw[512*128];
__device__ __align__(256) float g_h[M_ROWS*512];
__device__ __align__(256) float g_xp[M_ROWS*1536];
__device__ __align__(256) float g_f1[M_ROWS*512];
__device__ __align__(256) float g_f2[M_ROWS*512];
// aux contributions: [pair = b*50+blk][N]
__device__ __align__(256) float g_xadd2[200*1536];
__device__ __align__(256) float g_xaddf1[200*512];
__device__ __align__(256) float g_xaddf2[200*512];
// per-phase, per-batch double-buffered h state: [(phase*4+b)][buf][512]
__device__ __align__(256) float g_stb[8][2][512];
// per-phase, per-batch barrier counters, one 128B line each
__device__ __align__(128) unsigned g_cnt[8*32];

// ---------------- f32x2 / sync / math helpers ----------------
__device__ __forceinline__ ull pack2(float x, float y) {
    ull r; asm("mov.b64 %0, {%1,%2};" : "=l"(r) : "f"(x), "f"(y)); return r;
}
__device__ __forceinline__ ull dup2(float x) {
    ull r; unsigned u = __float_as_uint(x);
    asm("mov.b64 %0, {%1,%1};" : "=l"(r) : "r"(u)); return r;
}
__device__ __forceinline__ float2 unpack2(ull v) {
    float2 f; asm("mov.b64 {%0,%1}, %2;" : "=f"(f.x), "=f"(f.y) : "l"(v)); return f;
}
__device__ __forceinline__ void fma2(ull& d, ull a, ull b) {
    asm("fma.rn.f32x2 %0, %1, %2, %0;" : "+l"(d) : "l"(a), "l"(b));
}
__device__ __forceinline__ ull add2(ull a, ull b) {
    ull r; asm("add.rn.f32x2 %0, %1, %2;" : "=l"(r) : "l"(a), "l"(b)); return r;
}
__device__ __forceinline__ unsigned ld_acq(unsigned* p) {
    unsigned v; asm volatile("ld.acquire.gpu.u32 %0, [%1];" : "=r"(v) : "l"(p) : "memory"); return v;
}
__device__ __forceinline__ void red_rel_add(unsigned* p, unsigned v) {
    asm volatile("red.release.gpu.global.add.u32 [%0], %1;" :: "l"(p), "r"(v) : "memory");
}
__device__ __forceinline__ float tanh_fast(float x) {
    float y; asm("tanh.approx.f32 %0, %1;" : "=f"(y) : "f"(x)); return y;
}
__device__ __forceinline__ float sig_fast(float x) {
    return fmaf(tanh_fast(0.5f * x), 0.5f, 0.5f);
}

// ---------------- reset (counters + all chain states) ----------------
__global__ void k_reset() {
    int i = blockIdx.x*blockDim.x + threadIdx.x;
    if (i < 8*32) g_cnt[i] = 0u;
    if (i < 8192) ((float*)g_stb)[i] = 0.f;
}

// ---------------- mel resnet: one CTA per (b,l) column ----------------
__global__ void k_resnet(const float* __restrict__ mels, const float* __restrict__ w_in,
                         const float* __restrict__ bn0g, const float* __restrict__ bn0b,
                         const float* __restrict__ rc1, const float* __restrict__ rc2,
                         const float* __restrict__ rbn1g, const float* __restrict__ rbn1b,
                         const float* __restrict__ rbn2g, const float* __restrict__ rbn2b,
                         const float* __restrict__ cw, const float* __restrict__ cb,
                         float* __restrict__ aux) {
    int b = blockIdx.x / 50, l = blockIdx.x % 50;
    int o = threadIdx.x;
    __shared__ float mcol[400];
    __shared__ float xs[128], hs[128];
    const float sc = rsqrtf(1.0f + 1e-5f);

    for (int i = o; i < 400; i += 128) {
        int c = i / 5, k = i - c*5;
        mcol[i] = mels[(b*80 + c)*54 + l + k];
    }
    __syncthreads();

    float acc = 0.f;
    const float* wr = w_in + o*400;
    #pragma unroll 8
    for (int i = 0; i < 400; i++) acc += mcol[i] * __ldg(&wr[i]);
    acc = acc*(bn0g[o]*sc) + bn0b[o];
    xs[o] = fmaxf(acc, 0.f);

    for (int ib = 0; ib < 10; ib++) {
        __syncthreads();
        const float* r1 = rc1 + (ib*128 + o)*128;
        float h1 = 0.f;
        #pragma unroll 8
        for (int c = 0; c < 128; c++) h1 += xs[c] * __ldg(&r1[c]);
        h1 = h1*(rbn1g[ib*128+o]*sc) + rbn1b[ib*128+o];
        hs[o] = fmaxf(h1, 0.f);
        __syncthreads();
        const float* r2 = rc2 + (ib*128 + o)*128;
        float h2 = 0.f;
        #pragma unroll 8
        for (int c = 0; c < 128; c++) h2 += hs[c] * __ldg(&r2[c]);
        h2 = h2*(rbn2g[ib*128+o]*sc) + rbn2b[ib*128+o];
        float xn = h2 + xs[o];
        __syncthreads();
        xs[o] = xn;
    }
    __syncthreads();
    float a = 0.f;
    const float* cwr = cw + o*128;
    #pragma unroll 8
    for (int c = 0; c < 128; c++) a += xs[c] * __ldg(&cwr[c]);
    aux[(b*128 + o)*50 + l] = a + cb[o];
}

// ---------------- upsample stage ----------------
__global__ void k_upstage(const float* __restrict__ in, const float* __restrict__ w,
                          float* __restrict__ out, int L, int s, int K, int total) {
    int i = blockIdx.x*256 + threadIdx.x;
    if (i >= total) return;
    int Ls = L*s;
    int row = i / Ls, o = i - row*Ls;
    float acc = 0.f;
    for (int tap = 0; tap < K; tap++) {
        int p = o + tap - s;
        if (p >= 0 && p < Ls) acc += __ldg(&w[tap]) * __ldg(&in[row*L + p/s]);
    }
    out[i] = acc;
}

// ---------------- build padded input matrix for I-layer (M x 128) ----------------
__global__ void k_prep_in(const float* __restrict__ x, float* __restrict__ out) {
    int i = blockIdx.x*256 + threadIdx.x;
    if (i >= M_ROWS*128) return;
    int m = i >> 7, k = i & 127;
    int b = m / T_SZ, t = m - b*T_SZ;
    float v;
    if (k == 0)        v = x[m];
    else if (k <= 80)  v = g_up3[(b*80 + (k-1))*13824 + 512 + t];
    else if (k <= 112) v = g_aux[(b*128 + (k-81))*50 + t/256];
    else               v = 0.f;
    out[i] = v;
}

__global__ void k_pad_iw(const float* __restrict__ iw, float* __restrict__ o) {
    int i = blockIdx.x*256 + threadIdx.x;
    if (i >= 512*128) return;
    int n = i >> 7, k = i & 127;
    o[i] = (k < 113) ? iw[n*113 + k] : 0.f;
}

// ---------------- aux contribution: xadd[p][n] = sum_k W[n][512+k]*aux[b][aoff+k][blk]
// p = b*50 + blk; 200 pairs, K=32.
__global__ void k_xadd(const float* __restrict__ W, int ldw, int aoff, int N,
                       float* __restrict__ out) {
    int i = blockIdx.x*256 + threadIdx.x;
    if (i >= 200*N) return;
    int p = i / N, n = i - p*N;
    int b = p / 50, blk = p - b*50;
    const float* wr = W + (size_t)n*ldw + 512;
    float acc = 0.f;
    #pragma unroll 8
    for (int k = 0; k < 32; k++)
        acc += __ldg(&wr[k]) * __ldg(&g_aux[(b*128 + aoff + k)*50 + blk]);
    out[i] = acc;
}

// ---------------- GEMM: C[m][n] = A[m,:K].B[n,:K] + bias[n] (+xadd[b,blk][n]), relu?
// R14-proven double-buffered smem + register prefetch, ONE syncthreads per K-tile.
// lda/ldb allow strided rows (B rows may live inside 544-wide weights).
__global__ void __launch_bounds__(256) k_gemm(
        const float* __restrict__ A, int lda,
        const float* __restrict__ B, int ldb,
        const float* __restrict__ bias, const float* __restrict__ xadd,
        float* __restrict__ C, int N, int K, int relu) {
    __shared__ float As[2][16][132];
    __shared__ float Bs[2][16][132];
    int tid = threadIdx.x;
    int m0 = blockIdx.y*128, n0 = blockIdx.x*128;
    int tx = tid & 15, ty = tid >> 4;

    int row0 = tid >> 2,          kq0 = (tid & 3) * 4;
    int row1 = (tid + 256) >> 2,  kq1 = ((tid + 256) & 3) * 4;

    ull acc[8][4];
    #pragma unroll
    for (int i = 0; i < 8; i++)
        #pragma unroll
        for (int j = 0; j < 4; j++) acc[i][j] = 0ull;

    {
        float4 va0 = *(const float4*)&A[(size_t)(m0+row0)*lda + kq0];
        float4 va1 = *(const float4*)&A[(size_t)(m0+row1)*lda + kq1];
        float4 vb0 = *(const float4*)&B[(size_t)(n0+row0)*ldb + kq0];
        float4 vb1 = *(const float4*)&B[(size_t)(n0+row1)*ldb + kq1];
        As[0][kq0+0][row0] = va0.x; As[0][kq0+1][row0] = va0.y;
        As[0][kq0+2][row0] = va0.z; As[0][kq0+3][row0] = va0.w;
        As[0][kq1+0][row1] = va1.x; As[0][kq1+1][row1] = va1.y;
        As[0][kq1+2][row1] = va1.z; As[0][kq1+3][row1] = va1.w;
        Bs[0][kq0+0][row0] = vb0.x; Bs[0][kq0+1][row0] = vb0.y;
        Bs[0][kq0+2][row0] = vb0.z; Bs[0][kq0+3][row0] = vb0.w;
        Bs[0][kq1+0][row1] = vb1.x; Bs[0][kq1+1][row1] = vb1.y;
        Bs[0][kq1+2][row1] = vb1.z; Bs[0][kq1+3][row1] = vb1.w;
    }
    __syncthreads();

    int p = 0;
    for (int kb = 0; kb < K; kb += 16) {
        float4 ra0, ra1, rb0, rb1;
        bool more = (kb + 16 < K);
        if (more) {
            ra0 = *(const float4*)&A[(size_t)(m0+row0)*lda + kb + 16 + kq0];
            ra1 = *(const float4*)&A[(size_t)(m0+row1)*lda + kb + 16 + kq1];
            rb0 = *(const float4*)&B[(size_t)(n0+row0)*ldb + kb + 16 + kq0];
            rb1 = *(const float4*)&B[(size_t)(n0+row1)*ldb + kb + 16 + kq1];
        }

        #pragma unroll
        for (int kk = 0; kk < 16; kk++) {
            float a[8];
            *(float4*)&a[0] = *(const float4*)&As[p][kk][ty*8];
            *(float4*)&a[4] = *(const float4*)&As[p][kk][ty*8+4];
            const ull* bp = (const ull*)&Bs[p][kk][tx*8];
            ull b2[4];
            #pragma unroll
            for (int j = 0; j < 4; j++) b2[j] = bp[j];
            #pragma unroll
            for (int i = 0; i < 8; i++) {
                ull ad = pack2(a[i], a[i]);
                #pragma unroll
                for (int j = 0; j < 4; j++) fma2(acc[i][j], ad, b2[j]);
            }
        }

        if (more) {
            int q = p ^ 1;
            As[q][kq0+0][row0] = ra0.x; As[q][kq0+1][row0] = ra0.y;
            As[q][kq0+2][row0] = ra0.z; As[q][kq0+3][row0] = ra0.w;
            As[q][kq1+0][row1] = ra1.x; As[q][kq1+1][row1] = ra1.y;
            As[q][kq1+2][row1] = ra1.z; As[q][kq1+3][row1] = ra1.w;
            Bs[q][kq0+0][row0] = rb0.x; Bs[q][kq0+1][row0] = rb0.y;
            Bs[q][kq0+2][row0] = rb0.z; Bs[q][kq0+3][row0] = rb0.w;
            Bs[q][kq1+0][row1] = rb1.x; Bs[q][kq1+1][row1] = rb1.y;
            Bs[q][kq1+2][row1] = rb1.z; Bs[q][kq1+3][row1] = rb1.w;
            __syncthreads();
            p = q;
        }
    }

    #pragma unroll
    for (int i = 0; i < 8; i++) {
        int m = m0 + ty*8 + i;
        const float* xrow = nullptr;
        if (xadd) {
            int bb = m / T_SZ, blk = (m - bb*T_SZ) >> 8;
            xrow = xadd + (size_t)(bb*50 + blk)*N;
        }
        float* cp = &C[(size_t)m*N + n0 + tx*8];
        #pragma unroll
        for (int j = 0; j < 4; j++) {
            float2 v = unpack2(acc[i][j]);
            float2 bb2 = *(const float2*)&bias[n0 + tx*8 + 2*j];
            v.x += bb2.x; v.y += bb2.y;
            if (xadd) {
                float2 xa = *(const float2*)&xrow[n0 + tx*8 + 2*j];
                v.x += xa.x; v.y += xa.y;
            }
            if (relu) { v.x = fmaxf(v.x, 0.f); v.y = fmaxf(v.y, 0.f); }
            *(float2*)&cp[2*j] = v;
        }
    }
}

// ---------------- batch-split persistent GRU (R14 proven — frozen) ----------------
__global__ void __launch_bounds__(256,1) k_gru_b(
        const float* __restrict__ whh, const float* __restrict__ bhh,
        const float* __restrict__ xp, float* __restrict__ hio,
        float* __restrict__ st, unsigned* __restrict__ cnt) {
    const int lane = threadIdx.x & 31;
    const int wid = threadIdx.x >> 5;         // 0..7
    const int tid = threadIdx.x;
    const int b = blockIdx.x >> 5;            // batch chain 0..3
    const int cic = blockIdx.x & 31;          // cta within chain
    const int h0 = cic*16 + wid*2;            // this warp's h-pair

    float* stb = st + b*1024;                 // [2][512]
    unsigned* cb = cnt + b*32;                // own 128B line

    __shared__ __align__(16) float s_h[512];

    ull wp[3][16];
    #pragma unroll
    for (int g = 0; g < 3; g++) {
        const float* w0 = whh + (size_t)(g*512 + h0)*512;
        const float* w1 = w0 + 512;
        #pragma unroll
        for (int j128 = 0; j128 < 4; j128++)
            #pragma unroll
            for (int q = 0; q < 4; q++) {
                int j = lane*4 + q + j128*128;
                wp[g][j128*4+q] = pack2(__ldg(&w0[j]), __ldg(&w1[j]));
            }
    }
    const float br0 = __ldg(&bhh[h0]),      br1 = __ldg(&bhh[h0+1]);
    const float bz0 = __ldg(&bhh[512+h0]),  bz1 = __ldg(&bhh[512+h0+1]);
    const float bn0 = __ldg(&bhh[1024+h0]), bn1 = __ldg(&bhh[1024+h0+1]);

    float2 hprev = make_float2(0.f, 0.f);
    float2 xr, xz, xn, hres;
    if (lane == 0) {
        size_t xb = (size_t)(b*T_SZ + 0)*1536 + h0;
        xr   = *(const float2*)&xp[xb];
        xz   = *(const float2*)&xp[xb + 512];
        xn   = *(const float2*)&xp[xb + 1024];
        hres = *(const float2*)&hio[(size_t)(b*T_SZ + 0)*512 + h0];
    }

    for (int t = 0; t < T_SZ; t++) {
        if (tid < 128)
            *(float4*)&s_h[tid*4] = __ldcg((const float4*)(stb + (t & 1)*512) + tid);
        __syncthreads();

        ull acc[3] = {0ull, 0ull, 0ull};
        #pragma unroll
        for (int j128 = 0; j128 < 4; j128++) {
            float4 hv = *(const float4*)&s_h[lane*4 + j128*128];
            #pragma unroll
            for (int q = 0; q < 4; q++) {
                float hq = (q == 0) ? hv.x : (q == 1) ? hv.y : (q == 2) ? hv.z : hv.w;
                ull hd = dup2(hq);
                #pragma unroll
                for (int g = 0; g < 3; g++) fma2(acc[g], wp[g][j128*4+q], hd);
            }
        }
        #pragma unroll
        for (int g = 0; g < 3; g++)
            #pragma unroll
            for (int off = 16; off > 0; off >>= 1)
                acc[g] = add2(acc[g], __shfl_xor_sync(0xffffffffu, acc[g], off));

        float2 hnew = hprev;
        if (lane == 0) {
            float2 pr = unpack2(acc[0]);
            float2 pz = unpack2(acc[1]);
            float2 pn = unpack2(acc[2]);
            float r0 = sig_fast(xr.x + pr.x + br0);
            float z0 = sig_fast(xz.x + pz.x + bz0);
            float n0 = tanh_fast(xn.x + r0*(pn.x + bn0));
            float r1 = sig_fast(xr.y + pr.y + br1);
            float z1 = sig_fast(xz.y + pz.y + bz1);
            float n1 = tanh_fast(xn.y + r1*(pn.y + bn1));
            hnew.x = (1.f - z0)*n0 + z0*hprev.x;
            hnew.y = (1.f - z1)*n1 + z1*hprev.y;
            hprev = hnew;
            *(float2*)&stb[((t+1) & 1)*512 + h0] = hnew;
        }

        __syncthreads();
        if (tid == 0) red_rel_add(cb, 1u);

        if (lane == 0) {
            *(float2*)&hio[(size_t)(b*T_SZ + t)*512 + h0] =
                make_float2(hres.x + hnew.x, hres.y + hnew.y);
            if (t + 1 < T_SZ) {
                size_t xb = (size_t)(b*T_SZ + t + 1)*1536 + h0;
                xr   = *(const float2*)&xp[xb];
                xz   = *(const float2*)&xp[xb + 512];
                xn   = *(const float2*)&xp[xb + 1024];
                hres = *(const float2*)&hio[(size_t)(b*T_SZ + t + 1)*512 + h0];
            }
        }

        if (t + 1 < T_SZ) {
            if (tid == 0) {
                unsigned tgt = (unsigned)(t + 1) * (unsigned)CCTA;
                while (ld_acq(cb) < tgt) {}
            }
            __syncthreads();
        }
    }
}

// ---------------- host ----------------
static float* sym_addr(const void* s) {
    void* p = nullptr;
    cudaGetSymbolAddress(&p, s);
    return (float*)p;
}

extern "C" void kernel_launch(void* const* d_in, const int* in_sizes, int n_in,
                              void* d_out, int out_size) {
    const float* x        = (const float*)d_in[0];
    const float* mels     = (const float*)d_in[1];
    const float* conv_in_w= (const float*)d_in[2];
    const float* bn0_g    = (const float*)d_in[3];
    const float* bn0_b    = (const float*)d_in[4];
    const float* res_c1   = (const float*)d_in[5];
    const float* res_c2   = (const float*)d_in[6];
    const float* rbn1_g   = (const float*)d_in[7];
    const float* rbn1_b   = (const float*)d_in[8];
    const float* rbn2_g   = (const float*)d_in[9];
    const float* rbn2_b   = (const float*)d_in[10];
    const float* conv_ow  = (const float*)d_in[11];
    const float* conv_ob  = (const float*)d_in[12];
    const float* up_w0    = (const float*)d_in[13];
    const float* up_w1    = (const float*)d_in[14];
    const float* up_w2    = (const float*)d_in[15];
    const float* I_w      = (const float*)d_in[16];
    const float* I_b      = (const float*)d_in[17];
    const float* r1_wih   = (const float*)d_in[18];
    const float* r1_whh   = (const float*)d_in[19];
    const float* r1_bih   = (const float*)d_in[20];
    const float* r1_bhh   = (const float*)d_in[21];
    const float* r2_wih   = (const float*)d_in[22];
    const float* r2_whh   = (const float*)d_in[23];
    const float* r2_bih   = (const float*)d_in[24];
    const float* r2_bhh   = (const float*)d_in[25];
    const float* fc1_w    = (const float*)d_in[26];
    const float* fc1_b    = (const float*)d_in[27];
    const float* fc2_w    = (const float*)d_in[28];
    const float* fc2_b    = (const float*)d_in[29];
    const float* fc3_w    = (const float*)d_in[30];
    const float* fc3_b    = (const float*)d_in[31];
    float* out = (float*)d_out;

    float* p_aux = sym_addr(g_aux);
    float* p_up1 = sym_addr(g_up1);
    float* p_up2 = sym_addr(g_up2);
    float* p_up3 = sym_addr(g_up3);
    float* p_in0 = sym_addr(g_in0);
    float* p_iw  = sym_addr(g_iw);
    float* p_h   = sym_addr(g_h);
    float* p_xp  = sym_addr(g_xp);
    float* p_f1  = sym_addr(g_f1);
    float* p_f2  = sym_addr(g_f2);
    float* p_x2  = sym_addr(g_xadd2);
    float* p_xf1 = sym_addr(g_xaddf1);
    float* p_xf2 = sym_addr(g_xaddf2);
    float* p_st  = sym_addr(g_stb);
    unsigned* p_cnt = (unsigned*)sym_addr(g_cnt);

    // 1. aux (mel resnet) and upsample chain
    k_resnet<<<200, 128>>>(mels, conv_in_w, bn0_g, bn0_b, res_c1, res_c2,
                           rbn1_g, rbn1_b, rbn2_g, rbn2_b, conv_ow, conv_ob, p_aux);
    k_upstage<<<(4*80*216 + 255)/256, 256>>>(mels, up_w0, p_up1, 54, 4, 9, 4*80*216);
    k_upstage<<<(4*80*1728 + 255)/256, 256>>>(p_up1, up_w1, p_up2, 216, 8, 17, 4*80*1728);
    k_upstage<<<(4*80*13824 + 255)/256, 256>>>(p_up2, up_w2, p_up3, 1728, 8, 17, 4*80*13824);

    // 1b. aux contributions (replace all k_cat concats)
    k_xadd<<<(200*1536 + 255)/256, 256>>>(r2_wih, 544, 32, 1536, p_x2);
    k_xadd<<<(200*512 + 255)/256, 256>>>(fc1_w, 544, 64, 512, p_xf1);
    k_xadd<<<(200*512 + 255)/256, 256>>>(fc2_w, 544, 96, 512, p_xf2);

    // 2. I layer: h0 = [x | m_up | a1] @ I_w.T + I_b
    k_pad_iw<<<(512*128 + 255)/256, 256>>>(I_w, p_iw);
    k_prep_in<<<(M_ROWS*128)/256, 256>>>(x, p_in0);
    k_gemm<<<dim3(4, 400), 256>>>(p_in0, 128, p_iw, 128, I_b, nullptr, p_h, 512, 128, 0);

    // 3. reset chain states + counters (both phases)
    k_reset<<<32, 256>>>();

    // 4. GRU1: xp1 GEMM then 4 concurrent batch chains (h = ys1 + h0)
    k_gemm<<<dim3(12, 400), 256>>>(p_h, 512, r1_wih, 512, r1_bih, nullptr, p_xp, 1536, 512, 0);
    k_gru_b<<<4*CCTA, 256>>>(r1_whh, r1_bhh, p_xp, p_h, p_st, p_cnt);

    // 5. GRU2: xp2 = h@wih[:,:512].T + xadd2 + b (no cat), then chains
    k_gemm<<<dim3(12, 400), 256>>>(p_h, 512, r2_wih, 544, r2_bih, p_x2, p_xp, 1536, 512, 0);
    k_gru_b<<<4*CCTA, 256>>>(r2_whh, r2_bhh, p_xp, p_h, p_st + 4*1024, p_cnt + 4*32);

    // 6. fc1 / fc2 / fc3 (aux terms folded via xadd)
    k_gemm<<<dim3(4, 400), 256>>>(p_h, 512, fc1_w, 544, fc1_b, p_xf1, p_f1, 512, 512, 1);
    k_gemm<<<dim3(4, 400), 256>>>(p_f1, 512, fc2_w, 544, fc2_b, p_xf2, p_f2, 512, 512, 1);
    k_gemm<<<dim3(8, 400), 256>>>(p_f2, 512, fc3_w, 512, fc3_b, nullptr, out, 1024, 512, 0);
}